// round 14
// baseline (speedup 1.0000x reference)
#include <cuda_runtime.h>
#include <cuda_bf16.h>
#include <cstdint>

typedef unsigned long long ull;
typedef unsigned int u32;

#define NB 512
#define NT 512
#define NC 64
#define HALF_T 256        // fw owns t in [0,256); bw owns [256,512)
#define PAIRS 4           // batches per CTA
#define THREADS 256       // 8 warps = 4 (fw,bw) pairs
#define FULLMASK 0xffffffffu
#define LN2F 0.6931471805599453f

__device__ float    g_partial[NB];
__device__ unsigned g_done;

static __device__ __forceinline__ __nv_bfloat162 u2b(u32 u) {
    __nv_bfloat162 r; *reinterpret_cast<u32*>(&r) = u; return r;
}
static __device__ __forceinline__ u32 b2u(__nv_bfloat162 b) {
    return *reinterpret_cast<u32*>(&b);
}

// 64-wide GEMV via warp shuffle broadcast — NO shared memory, NO syncwarp.
// Lane k holds pp = bf16x2(v_2k, v_2k+1). Broadcasting lane i gives all lanes
// (v_2i, v_2i+1); e2c0[i] = (E[2i][c0], E[2i+1][c0]) and e2c1 likewise, so
// 2 HFMA2 per broadcast accumulate both output columns. Both halves of each
// accumulator are partials of the SAME column; fold once at the end in f32.
#define GEMV64S(QX, QY) do {                                                     \
    u32 pu_ = b2u(pp);                                                           \
    __nv_bfloat162 a0_ = u2b(0u), a1_ = u2b(0u);                                 \
    __nv_bfloat162 c0_ = u2b(0u), c1_ = u2b(0u);                                 \
    _Pragma("unroll")                                                            \
    for (int i_ = 0; i_ < 32; i_ += 2) {                                         \
        u32 v0_ = __shfl_sync(FULLMASK, pu_, i_);                                \
        u32 v1_ = __shfl_sync(FULLMASK, pu_, i_ + 1);                            \
        a0_ = __hfma2(u2b(v0_), e2c0[i_],     a0_);                              \
        c0_ = __hfma2(u2b(v0_), e2c1[i_],     c0_);                              \
        a1_ = __hfma2(u2b(v1_), e2c0[i_ + 1], a1_);                              \
        c1_ = __hfma2(u2b(v1_), e2c1[i_ + 1], c1_);                              \
    }                                                                            \
    float2 fa_ = __bfloat1622float2(__hadd2(a0_, a1_));                          \
    float2 fc_ = __bfloat1622float2(__hadd2(c0_, c1_));                          \
    QX = fa_.x + fa_.y;                                                          \
    QY = fc_.x + fc_.y;                                                          \
} while (0)

// Exact power-of-2 renorm of f32 (px,py); p strictly positive.
#define RENORM2() do {                                                           \
    int mb_ = __reduce_max_sync(FULLMASK, __float_as_int(fmaxf(px, py)));        \
    int e_  = mb_ >> 23;                                                         \
    float inv_ = __int_as_float((254 - e_) << 23);   /* 2^(127-e), exact */      \
    px *= inv_; py *= inv_;                                                      \
    logZ += (float)(e_ - 127) * LN2F;                                            \
} while (0)

// Forward step: q = E^T p; masked: p = q * exp(emit_t). New pp = pack(p).
#define STEP_F(EM, M, REN) do {                                                  \
    float ex_ = __expf((EM).x), ey_ = __expf((EM).y);                            \
    float qx_, qy_; GEMV64S(qx_, qy_);                                           \
    if (M) { px = qx_ * ex_; py = qy_ * ey_; }                                   \
    if (REN) RENORM2();                                                          \
    pp = __floats2bfloat162_rn(px, py);                                          \
} while (0)

// Backward step: c = E v; masked: beta = c; propagate v' = beta*exp(emit_{u-1}).
#define STEP_B(EM, M, REN) do {                                                  \
    float ex_ = __expf((EM).x), ey_ = __expf((EM).y);                            \
    float qx_, qy_; GEMV64S(qx_, qy_);                                           \
    if (M) { px = qx_; py = qy_; }                                               \
    if (REN) RENORM2();                                                          \
    pp = __floats2bfloat162_rn(px * ex_, py * ey_);                              \
} while (0)

__global__ void __launch_bounds__(THREADS, 1) crf_forward(
    const float* __restrict__ emissions,   // [B, T, C]
    const int*   __restrict__ tags,        // [B, T]
    const int*   __restrict__ mask,        // [B, T]
    const float* __restrict__ trans,       // [C, C]
    const float* __restrict__ startt,      // [C]
    const float* __restrict__ endt,        // [C]
    float*       __restrict__ out)         // [1]
{
    __shared__ __align__(8) float2 bbuf[PAIRS][32];   // beta_255 (f32)
    __shared__ float s_logZb[PAIRS];
    __shared__ float s_numb[PAIRS];
    __shared__ bool  s_last;

    const int wid  = threadIdx.x >> 5;
    const int lane = threadIdx.x & 31;
    const int pair = wid >> 1;
    const int role = wid & 1;                 // 0 = forward, 1 = backward
    const int b    = blockIdx.x * PAIRS + pair;
    const int j0   = lane * 2;

    const float* em = emissions + (size_t)b * NT * NC;
    const int*   tg = tags + (size_t)b * NT;
    const int*   mk = mask + (size_t)b * NT;

    float2 et2 = *(const float2*)(endt + j0);

    __nv_bfloat162 e2c0[32], e2c1[32];
    __nv_bfloat162 pp;                        // packed state (v_2lane, v_2lane+1)
    float px, py, logZ;

    if (role == 0) {
        // ========================= FORWARD (t = 0..255) =========================
        float2 em0  = *(const float2*)(em + j0);
        float2 emP0 = *(const float2*)(em + (size_t)1 * NC + j0);
        float2 emP1 = *(const float2*)(em + (size_t)2 * NC + j0);
        float2 emP2 = *(const float2*)(em + (size_t)3 * NC + j0);
        int4   mk03 = *(const int4*)(mk);
        int4   mc   = *(const int4*)(mk + 4);
        float2 emc0 = *(const float2*)(em + (size_t)4 * NC + j0);
        float2 emc1 = *(const float2*)(em + (size_t)5 * NC + j0);
        float2 emc2 = *(const float2*)(em + (size_t)6 * NC + j0);
        float2 emc3 = *(const float2*)(em + (size_t)7 * NC + j0);
        float2 st2  = *(const float2*)(startt + j0);

        // e2c0[k] = (exp T[2k][c0], exp T[2k+1][c0]); e2c1 likewise for c1.
#pragma unroll
        for (int k = 0; k < 32; k++) {
            float2 r0 = *(const float2*)(trans + (2 * k) * NC + j0);
            float2 r1 = *(const float2*)(trans + (2 * k + 1) * NC + j0);
            e2c0[k] = __floats2bfloat162_rn(__expf(r0.x), __expf(r1.x));
            e2c1[k] = __floats2bfloat162_rn(__expf(r0.y), __expf(r1.y));
        }

        // numerator (f32), first half: start term + t in [1, 256)
        float num = 0.f;
#pragma unroll 2
        for (int t = lane; t < HALF_T; t += 32) {
            int tt = tg[t];
            if (t > 0 && mk[t])
                num += trans[tg[t - 1] * NC + tt] + em[(size_t)t * NC + tt];
        }
#pragma unroll
        for (int o = 16; o > 0; o >>= 1)
            num += __shfl_down_sync(FULLMASK, num, o);
        if (lane == 0) {
            int t0 = tg[0];
            num += startt[t0] + em[t0];
        }

        // init t = 0 (values may be negative -> shfl fmax tree)
        float ax = st2.x + em0.x, ay = st2.y + em0.y;
        float m0 = fmaxf(ax, ay);
#pragma unroll
        for (int o = 16; o > 0; o >>= 1)
            m0 = fmaxf(m0, __shfl_xor_sync(FULLMASK, m0, o));
        logZ = m0;
        px = __expf(ax - m0);
        py = __expf(ay - m0);
        pp = __floats2bfloat162_rn(px, py);

        STEP_F(emP0, mk03.y, false);
        STEP_F(emP1, mk03.z, false);
        STEP_F(emP2, mk03.w, true);

#pragma unroll 1
        for (int t0 = 4; t0 < HALF_T; t0 += 4) {
            float2 en0 = emc0, en1 = emc1, en2 = emc2, en3 = emc3;
            int4   mn  = mc;
            if (t0 + 4 < HALF_T) {
                const float* p4 = em + (size_t)(t0 + 4) * NC + j0;
                en0 = *(const float2*)(p4);
                en1 = *(const float2*)(p4 + NC);
                en2 = *(const float2*)(p4 + 2 * NC);
                en3 = *(const float2*)(p4 + 3 * NC);
                mn  = *(const int4*)(mk + t0 + 4);
            }
            STEP_F(emc0, mc.x, false);
            STEP_F(emc1, mc.y, false);
            STEP_F(emc2, mc.z, false);
            STEP_F(emc3, mc.w, true);
            emc0 = en0; emc1 = en1; emc2 = en2; emc3 = en3; mc = mn;
        }

        __syncthreads();   // beta_255, logZb, num_b published by bw warp

        float2 bb = bbuf[pair][lane];
        float contrib = px * bb.x + py * bb.y;
#pragma unroll
        for (int o = 16; o > 0; o >>= 1)
            contrib += __shfl_down_sync(FULLMASK, contrib, o);
        if (lane == 0)
            g_partial[b] = logZ + s_logZb[pair] + __logf(contrib)
                           - (num + s_numb[pair]);
    } else {
        // ========================= BACKWARD (t = 511..256) ======================
        float2 emI  = *(const float2*)(em + (size_t)511 * NC + j0);  // e_511
        float2 eP0  = *(const float2*)(em + (size_t)510 * NC + j0);
        float2 eP1  = *(const float2*)(em + (size_t)509 * NC + j0);
        float2 eP2  = *(const float2*)(em + (size_t)508 * NC + j0);
        int mk511 = mk[511], mk510 = mk[510], mk509 = mk[509];
        float2 be0 = *(const float2*)(em + (size_t)507 * NC + j0);
        float2 be1 = *(const float2*)(em + (size_t)506 * NC + j0);
        float2 be2 = *(const float2*)(em + (size_t)505 * NC + j0);
        float2 be3 = *(const float2*)(em + (size_t)504 * NC + j0);
        int m0g = mk[508], m1g = mk[507], m2g = mk[506], m3g = mk[505];
        int mk256 = mk[256];

        // Backward GEMV: q_c = sum_k E[c][k] v_k.
        // e2c0[k] = (exp T[c0][2k], exp T[c0][2k+1]); e2c1 for row c1.
#pragma unroll
        for (int k = 0; k < 32; k++) {
            float2 r0 = *(const float2*)(trans + j0 * NC + 2 * k);
            float2 r1 = *(const float2*)(trans + (j0 + 1) * NC + 2 * k);
            e2c0[k] = __floats2bfloat162_rn(__expf(r0.x), __expf(r0.y));
            e2c1[k] = __floats2bfloat162_rn(__expf(r1.x), __expf(r1.y));
        }

        // numerator (f32), second half + end term (needs full cnt)
        float num = 0.f;
        int   cnt = 0;
#pragma unroll 2
        for (int t = lane; t < NT; t += 32) {
            int m = mk[t];
            cnt += m;
            if (t >= HALF_T && m) {
                int tt = tg[t];
                num += trans[tg[t - 1] * NC + tt] + em[(size_t)t * NC + tt];
            }
        }
        cnt = __reduce_add_sync(FULLMASK, cnt);
#pragma unroll
        for (int o = 16; o > 0; o >>= 1)
            num += __shfl_down_sync(FULLMASK, num, o);
        if (lane == 0)
            s_numb[pair] = num + endt[tg[cnt - 1]];

        // init: beta_511 = exp(end); propagate v_511 = e_511 * beta_511
        logZ = 0.f;
        px = __expf(et2.x);
        py = __expf(et2.y);
        pp = __floats2bfloat162_rn(px * __expf(emI.x), py * __expf(emI.y));

        STEP_B(eP0, mk511, false);
        STEP_B(eP1, mk510, false);
        STEP_B(eP2, mk509, true);

#pragma unroll 1
        for (int u0 = 508; u0 >= 260; u0 -= 4) {
            float2 bn0 = be0, bn1 = be1, bn2 = be2, bn3 = be3;
            int n0 = m0g, n1 = m1g, n2 = m2g, n3 = m3g;
            if (u0 > 260) {
                const int u1 = u0 - 4;
                const float* p4 = em + (size_t)(u1 - 4) * NC + j0;
                bn0 = *(const float2*)(p4 + 3 * NC);   // e_{u1-1}
                bn1 = *(const float2*)(p4 + 2 * NC);   // e_{u1-2}
                bn2 = *(const float2*)(p4 + NC);       // e_{u1-3}
                bn3 = *(const float2*)(p4);            // e_{u1-4}
                n0 = mk[u1]; n1 = mk[u1 - 1]; n2 = mk[u1 - 2]; n3 = mk[u1 - 3];
            }
            STEP_B(be0, m0g, false);
            STEP_B(be1, m1g, false);
            STEP_B(be2, m2g, false);
            STEP_B(be3, m3g, true);
            be0 = bn0; be1 = bn1; be2 = bn2; be3 = bn3;
            m0g = n0; m1g = n1; m2g = n2; m3g = n3;
        }

        // final step u = 256: select only (no emission, no propagate)
        {
            float qx_, qy_;
            GEMV64S(qx_, qy_);
            if (mk256) { px = qx_; py = qy_; }
        }
        bbuf[pair][lane] = make_float2(px, py);
        if (lane == 0) s_logZb[pair] = logZ;

        __syncthreads();   // matches fw warp's barrier
    }

    // ---- fused final reduction: last CTA to finish reduces all 512 ----
    __syncthreads();
    if (threadIdx.x == 0) {
        __threadfence();
        unsigned prev = atomicAdd(&g_done, 1u);
        s_last = (prev == gridDim.x - 1);
    }
    __syncthreads();
    if (s_last && wid == 0) {
        __threadfence();
        float s = 0.f;
        const float4* gp = (const float4*)g_partial;
#pragma unroll
        for (int k = 0; k < 4; k++) {
            float4 v = __ldcg(gp + lane + 32 * k);
            s += (v.x + v.y) + (v.z + v.w);
        }
#pragma unroll
        for (int o = 16; o > 0; o >>= 1)
            s += __shfl_down_sync(FULLMASK, s, o);
        if (lane == 0) {
            out[0] = s * (1.0f / (float)NB);
            g_done = 0;   // reset for next graph replay (deterministic)
        }
    }
}

extern "C" void kernel_launch(void* const* d_in, const int* in_sizes, int n_in,
                              void* d_out, int out_size) {
    const float* emissions = (const float*)d_in[0];
    const int*   tags      = (const int*)d_in[1];
    const int*   mask      = (const int*)d_in[2];
    const float* trans     = (const float*)d_in[3];
    const float* startt    = (const float*)d_in[4];
    const float* endt      = (const float*)d_in[5];
    (void)in_sizes; (void)n_in; (void)out_size;

    crf_forward<<<NB / PAIRS, THREADS>>>(emissions, tags, mask, trans, startt,
                                         endt, (float*)d_out);
}

// round 15
// speedup vs baseline: 1.0121x; 1.0121x over previous
#include <cuda_runtime.h>
#include <cuda_bf16.h>
#include <cstdint>

typedef unsigned long long ull;
typedef unsigned int u32;

#define NB 512
#define NT 512
#define NC 64
#define HALF_T 256        // fw owns t in [0,256); bw owns [256,512)
#define PAIRS 4           // batches per CTA
#define THREADS 256       // 8 warps = 4 (fw,bw) pairs
#define FULLMASK 0xffffffffu
#define LN2F 0.6931471805599453f

__device__ float    g_partial[NB];
__device__ unsigned g_done;

static __device__ __forceinline__ __nv_bfloat162 u2b(u32 u) {
    __nv_bfloat162 r; *reinterpret_cast<u32*>(&r) = u; return r;
}
static __device__ __forceinline__ u32 b2u(__nv_bfloat162 b) {
    return *reinterpret_cast<u32*>(&b);
}

// 64-wide GEMV, packed-pair layout (R13 exchange: 8x broadcast LDS.128).
// Buffer entry j = bf16x2(v_2j, v_2j+1). e2c0[k] = (E[2k][c0], E[2k+1][c0]),
// e2c1 likewise for column c1. Fold stays ENTIRELY in packed bf16:
// a=(a0+a1), c=(c0+c1); PRMT-interleave lows/highs; one HADD2 gives
// QOUT = bf16x2(q_c0, q_c1). No f32 conversions on the hot path.
#define GEMV64P(SRC, QOUT) do {                                                  \
    const uint4* pb_ = (const uint4*)(SRC);                                      \
    __nv_bfloat162 a0_ = u2b(0u), a1_ = u2b(0u);                                 \
    __nv_bfloat162 c0_ = u2b(0u), c1_ = u2b(0u);                                 \
    _Pragma("unroll")                                                            \
    for (int k_ = 0; k_ < 8; k_++) {                                             \
        uint4 v_ = pb_[k_];                                                      \
        a0_ = __hfma2(u2b(v_.x), e2c0[4 * k_ + 0], a0_);                         \
        c0_ = __hfma2(u2b(v_.x), e2c1[4 * k_ + 0], c0_);                         \
        a1_ = __hfma2(u2b(v_.y), e2c0[4 * k_ + 1], a1_);                         \
        c1_ = __hfma2(u2b(v_.y), e2c1[4 * k_ + 1], c1_);                         \
        a0_ = __hfma2(u2b(v_.z), e2c0[4 * k_ + 2], a0_);                         \
        c0_ = __hfma2(u2b(v_.z), e2c1[4 * k_ + 2], c0_);                         \
        a1_ = __hfma2(u2b(v_.w), e2c0[4 * k_ + 3], a1_);                         \
        c1_ = __hfma2(u2b(v_.w), e2c1[4 * k_ + 3], c1_);                         \
    }                                                                            \
    u32 au_ = b2u(__hadd2(a0_, a1_));                                            \
    u32 cu_ = b2u(__hadd2(c0_, c1_));                                            \
    __nv_bfloat162 lo_ = u2b(__byte_perm(au_, cu_, 0x5410)); /* (a.x, c.x) */    \
    __nv_bfloat162 hi_ = u2b(__byte_perm(au_, cu_, 0x7632)); /* (a.y, c.y) */    \
    QOUT = __hadd2(lo_, hi_);                                                    \
} while (0)

// Exact power-of-2 renorm of packed-positive pp (bf16x2). bf16 bit pattern of
// a positive value is monotonic as an int -> REDUX max over the 16-bit bits.
#define RENORM_PP() do {                                                         \
    u32 pu_ = b2u(pp);                                                           \
    u32 sw_ = __byte_perm(pu_, pu_, 0x1032);       /* swap 16-bit halves */      \
    u32 mB_ = b2u(__hmax2(pp, u2b(sw_))) & 0xFFFFu;                              \
    u32 mx_ = (u32)__reduce_max_sync(FULLMASK, (int)mB_);                        \
    int e_  = (int)(mx_ >> 7) & 0xFF;              /* biased bf16 exponent */    \
    u32 sb_ = (u32)(254 - e_) << 7;                /* bf16 bits of 2^(127-e) */  \
    pp = __hmul2(pp, u2b(sb_ | (sb_ << 16)));                                    \
    logZ += (float)(e_ - 127) * LN2F;                                            \
} while (0)

// Forward step: q = E^T p; masked: p = q * exp(emit_t). All packed bf16.
#define STEP_F(EM, M, REN) do {                                                  \
    __nv_bfloat162 ee_ =                                                         \
        __floats2bfloat162_rn(__expf((EM).x), __expf((EM).y));                   \
    __nv_bfloat162 q_; GEMV64P(pbuf[wid][cur], q_);                              \
    if (M) pp = __hmul2(q_, ee_);                                                \
    if (REN) RENORM_PP();                                                        \
    cur ^= 1;                                                                    \
    pbuf[wid][cur][lane] = b2u(pp);                                              \
    __syncwarp();                                                                \
} while (0)

// Backward step: c = E v; masked: beta = c; store v' = beta * exp(emit_{u-1}).
#define STEP_B(EM, M, REN) do {                                                  \
    __nv_bfloat162 ee_ =                                                         \
        __floats2bfloat162_rn(__expf((EM).x), __expf((EM).y));                   \
    __nv_bfloat162 q_; GEMV64P(pbuf[wid][cur], q_);                              \
    if (M) pp = q_;                                                              \
    if (REN) RENORM_PP();                                                        \
    cur ^= 1;                                                                    \
    pbuf[wid][cur][lane] = b2u(__hmul2(pp, ee_));                                \
    __syncwarp();                                                                \
} while (0)

__global__ void __launch_bounds__(THREADS, 1) crf_forward(
    const float* __restrict__ emissions,   // [B, T, C]
    const int*   __restrict__ tags,        // [B, T]
    const int*   __restrict__ mask,        // [B, T]
    const float* __restrict__ trans,       // [C, C]
    const float* __restrict__ startt,      // [C]
    const float* __restrict__ endt,        // [C]
    float*       __restrict__ out)         // [1]
{
    // Per-warp double-buffered packed bf16 state: entry j = (v_2j, v_2j+1).
    __shared__ __align__(16) u32    pbuf[8][2][32];
    __shared__ __align__(8)  float2 bbuf[PAIRS][32];   // beta_255 (f32)
    __shared__ float s_logZb[PAIRS];
    __shared__ float s_numb[PAIRS];
    __shared__ bool  s_last;

    const int wid  = threadIdx.x >> 5;
    const int lane = threadIdx.x & 31;
    const int pair = wid >> 1;
    const int role = wid & 1;                 // 0 = forward, 1 = backward
    const int b    = blockIdx.x * PAIRS + pair;
    const int j0   = lane * 2;

    const float* em = emissions + (size_t)b * NT * NC;
    const int*   tg = tags + (size_t)b * NT;
    const int*   mk = mask + (size_t)b * NT;

    float2 et2 = *(const float2*)(endt + j0);

    __nv_bfloat162 e2c0[32], e2c1[32];
    __nv_bfloat162 pp;          // packed state: this warp's (v_2lane, v_2lane+1)
    int   cur = 0;
    float logZ;

    if (role == 0) {
        // ========================= FORWARD (t = 0..255) =========================
        float2 em0  = *(const float2*)(em + j0);
        float2 emP0 = *(const float2*)(em + (size_t)1 * NC + j0);
        float2 emP1 = *(const float2*)(em + (size_t)2 * NC + j0);
        float2 emP2 = *(const float2*)(em + (size_t)3 * NC + j0);
        int4   mk03 = *(const int4*)(mk);
        int4   mc   = *(const int4*)(mk + 4);
        float2 emc0 = *(const float2*)(em + (size_t)4 * NC + j0);
        float2 emc1 = *(const float2*)(em + (size_t)5 * NC + j0);
        float2 emc2 = *(const float2*)(em + (size_t)6 * NC + j0);
        float2 emc3 = *(const float2*)(em + (size_t)7 * NC + j0);
        float2 st2  = *(const float2*)(startt + j0);

        // e2c0[k] = (exp T[2k][c0], exp T[2k+1][c0]); e2c1 likewise for c1.
#pragma unroll
        for (int k = 0; k < 32; k++) {
            float2 r0 = *(const float2*)(trans + (2 * k) * NC + j0);
            float2 r1 = *(const float2*)(trans + (2 * k + 1) * NC + j0);
            e2c0[k] = __floats2bfloat162_rn(__expf(r0.x), __expf(r1.x));
            e2c1[k] = __floats2bfloat162_rn(__expf(r0.y), __expf(r1.y));
        }

        // numerator (f32), first half: start term + t in [1, 256)
        float num = 0.f;
#pragma unroll 2
        for (int t = lane; t < HALF_T; t += 32) {
            int tt = tg[t];
            if (t > 0 && mk[t])
                num += trans[tg[t - 1] * NC + tt] + em[(size_t)t * NC + tt];
        }
#pragma unroll
        for (int o = 16; o > 0; o >>= 1)
            num += __shfl_down_sync(FULLMASK, num, o);
        if (lane == 0) {
            int t0 = tg[0];
            num += startt[t0] + em[t0];
        }

        // init t = 0 (values may be negative -> shfl fmax tree)
        float ax = st2.x + em0.x, ay = st2.y + em0.y;
        float m0 = fmaxf(ax, ay);
#pragma unroll
        for (int o = 16; o > 0; o >>= 1)
            m0 = fmaxf(m0, __shfl_xor_sync(FULLMASK, m0, o));
        logZ = m0;
        pp = __floats2bfloat162_rn(__expf(ax - m0), __expf(ay - m0));
        pbuf[wid][0][lane] = b2u(pp);
        __syncwarp();

        STEP_F(emP0, mk03.y, false);
        STEP_F(emP1, mk03.z, false);
        STEP_F(emP2, mk03.w, true);

#pragma unroll 1
        for (int t0 = 4; t0 < HALF_T; t0 += 4) {
            float2 en0 = emc0, en1 = emc1, en2 = emc2, en3 = emc3;
            int4   mn  = mc;
            if (t0 + 4 < HALF_T) {
                const float* p4 = em + (size_t)(t0 + 4) * NC + j0;
                en0 = *(const float2*)(p4);
                en1 = *(const float2*)(p4 + NC);
                en2 = *(const float2*)(p4 + 2 * NC);
                en3 = *(const float2*)(p4 + 3 * NC);
                mn  = *(const int4*)(mk + t0 + 4);
            }
            STEP_F(emc0, mc.x, false);
            STEP_F(emc1, mc.y, false);
            STEP_F(emc2, mc.z, false);
            STEP_F(emc3, mc.w, true);
            emc0 = en0; emc1 = en1; emc2 = en2; emc3 = en3; mc = mn;
        }

        __syncthreads();   // beta_255, logZb, num_b published by bw warp

        float2 pf = __bfloat1622float2(pp);
        float2 bb = bbuf[pair][lane];
        float contrib = pf.x * bb.x + pf.y * bb.y;
#pragma unroll
        for (int o = 16; o > 0; o >>= 1)
            contrib += __shfl_down_sync(FULLMASK, contrib, o);
        if (lane == 0)
            g_partial[b] = logZ + s_logZb[pair] + __logf(contrib)
                           - (num + s_numb[pair]);
    } else {
        // ========================= BACKWARD (t = 511..256) ======================
        float2 emI  = *(const float2*)(em + (size_t)511 * NC + j0);  // e_511
        float2 eP0  = *(const float2*)(em + (size_t)510 * NC + j0);
        float2 eP1  = *(const float2*)(em + (size_t)509 * NC + j0);
        float2 eP2  = *(const float2*)(em + (size_t)508 * NC + j0);
        int mk511 = mk[511], mk510 = mk[510], mk509 = mk[509];
        float2 be0 = *(const float2*)(em + (size_t)507 * NC + j0);
        float2 be1 = *(const float2*)(em + (size_t)506 * NC + j0);
        float2 be2 = *(const float2*)(em + (size_t)505 * NC + j0);
        float2 be3 = *(const float2*)(em + (size_t)504 * NC + j0);
        int m0g = mk[508], m1g = mk[507], m2g = mk[506], m3g = mk[505];
        int mk256 = mk[256];

        // Backward GEMV: q_c = sum_k E[c][k] v_k.
        // e2c0[k] = (exp T[c0][2k], exp T[c0][2k+1]); e2c1 for row c1.
#pragma unroll
        for (int k = 0; k < 32; k++) {
            float2 r0 = *(const float2*)(trans + j0 * NC + 2 * k);
            float2 r1 = *(const float2*)(trans + (j0 + 1) * NC + 2 * k);
            e2c0[k] = __floats2bfloat162_rn(__expf(r0.x), __expf(r0.y));
            e2c1[k] = __floats2bfloat162_rn(__expf(r1.x), __expf(r1.y));
        }

        // numerator (f32), second half + end term (needs full cnt)
        float num = 0.f;
        int   cnt = 0;
#pragma unroll 2
        for (int t = lane; t < NT; t += 32) {
            int m = mk[t];
            cnt += m;
            if (t >= HALF_T && m) {
                int tt = tg[t];
                num += trans[tg[t - 1] * NC + tt] + em[(size_t)t * NC + tt];
            }
        }
        cnt = __reduce_add_sync(FULLMASK, cnt);
#pragma unroll
        for (int o = 16; o > 0; o >>= 1)
            num += __shfl_down_sync(FULLMASK, num, o);
        if (lane == 0)
            s_numb[pair] = num + endt[tg[cnt - 1]];

        // init: beta_511 = exp(end); store v_511 = e_511 * beta_511
        logZ = 0.f;
        pp = __floats2bfloat162_rn(__expf(et2.x), __expf(et2.y));
        {
            __nv_bfloat162 eI =
                __floats2bfloat162_rn(__expf(emI.x), __expf(emI.y));
            pbuf[wid][0][lane] = b2u(__hmul2(pp, eI));
        }
        __syncwarp();

        STEP_B(eP0, mk511, false);
        STEP_B(eP1, mk510, false);
        STEP_B(eP2, mk509, true);

#pragma unroll 1
        for (int u0 = 508; u0 >= 260; u0 -= 4) {
            float2 bn0 = be0, bn1 = be1, bn2 = be2, bn3 = be3;
            int n0 = m0g, n1 = m1g, n2 = m2g, n3 = m3g;
            if (u0 > 260) {
                const int u1 = u0 - 4;
                const float* p4 = em + (size_t)(u1 - 4) * NC + j0;
                bn0 = *(const float2*)(p4 + 3 * NC);   // e_{u1-1}
                bn1 = *(const float2*)(p4 + 2 * NC);   // e_{u1-2}
                bn2 = *(const float2*)(p4 + NC);       // e_{u1-3}
                bn3 = *(const float2*)(p4);            // e_{u1-4}
                n0 = mk[u1]; n1 = mk[u1 - 1]; n2 = mk[u1 - 2]; n3 = mk[u1 - 3];
            }
            STEP_B(be0, m0g, false);
            STEP_B(be1, m1g, false);
            STEP_B(be2, m2g, false);
            STEP_B(be3, m3g, true);
            be0 = bn0; be1 = bn1; be2 = bn2; be3 = bn3;
            m0g = n0; m1g = n1; m2g = n2; m3g = n3;
        }

        // final step u = 256: select only (no emission, no store)
        {
            __nv_bfloat162 q_;
            GEMV64P(pbuf[wid][cur], q_);
            if (mk256) pp = q_;
        }
        bbuf[pair][lane] = __bfloat1622float2(pp);
        if (lane == 0) s_logZb[pair] = logZ;

        __syncthreads();   // matches fw warp's barrier
    }

    // ---- fused final reduction: last CTA to finish reduces all 512 ----
    __syncthreads();
    if (threadIdx.x == 0) {
        __threadfence();
        unsigned prev = atomicAdd(&g_done, 1u);
        s_last = (prev == gridDim.x - 1);
    }
    __syncthreads();
    if (s_last && wid == 0) {
        __threadfence();
        float s = 0.f;
        const float4* gp = (const float4*)g_partial;
#pragma unroll
        for (int k = 0; k < 4; k++) {
            float4 v = __ldcg(gp + lane + 32 * k);
            s += (v.x + v.y) + (v.z + v.w);
        }
#pragma unroll
        for (int o = 16; o > 0; o >>= 1)
            s += __shfl_down_sync(FULLMASK, s, o);
        if (lane == 0) {
            out[0] = s * (1.0f / (float)NB);
            g_done = 0;   // reset for next graph replay (deterministic)
        }
    }
}

extern "C" void kernel_launch(void* const* d_in, const int* in_sizes, int n_in,
                              void* d_out, int out_size) {
    const float* emissions = (const float*)d_in[0];
    const int*   tags      = (const int*)d_in[1];
    const int*   mask      = (const int*)d_in[2];
    const float* trans     = (const float*)d_in[3];
    const float* startt    = (const float*)d_in[4];
    const float* endt      = (const float*)d_in[5];
    (void)in_sizes; (void)n_in; (void)out_size;

    crf_forward<<<NB / PAIRS, THREADS>>>(emissions, tags, mask, trans, startt,
                                         endt, (float*)d_out);
}